// round 4
// baseline (speedup 1.0000x reference)
#include <cuda_runtime.h>

#define NM 1024
#define HH 256
#define WW 256
#define HWsz 65536

// Scratch (allocation-free: __device__ globals)
__device__ float g_boxes[NM * 4];
__device__ int   g_valid[NM];
__device__ int   g_kcnt;
__device__ int   g_klist[NM];
__device__ float g_kgate[NM];

// ---------------------------------------------------------------------------
// Kernel A: per-mask stats (unchanged from R3: 45.6us, DRAM 75.4%).
// ---------------------------------------------------------------------------
__global__ __launch_bounds__(256) void stats_kernel(const float* __restrict__ logits,
                                                    const float* __restrict__ iou) {
    int n = blockIdx.x;
    const float4* p = (const float4*)(logits + (size_t)n * HWsz);

    int hi = 0, lo = 0;
    int minX = WW, maxX = -1, minY = HH, maxY = -1;

    for (int k = threadIdx.x; k < HWsz / 8; k += 256) {
        float4 a = p[k];
        float4 b = p[k + HWsz / 8];
        {
            int lin = k << 2;
            int y = lin >> 8, x = lin & 255;
            hi += (a.x > 1.0f) + (a.y > 1.0f) + (a.z > 1.0f) + (a.w > 1.0f);
            lo += (a.x > -1.0f) + (a.y > -1.0f) + (a.z > -1.0f) + (a.w > -1.0f);
            unsigned m = (a.x > 0.0f ? 1u : 0u) | (a.y > 0.0f ? 2u : 0u) |
                         (a.z > 0.0f ? 4u : 0u) | (a.w > 0.0f ? 8u : 0u);
            if (m) {
                minY = min(minY, y); maxY = max(maxY, y);
                minX = min(minX, x + (__ffs(m) - 1));
                maxX = max(maxX, x + (31 - __clz(m)));
            }
        }
        {
            int lin = (k + HWsz / 8) << 2;
            int y = lin >> 8, x = lin & 255;
            hi += (b.x > 1.0f) + (b.y > 1.0f) + (b.z > 1.0f) + (b.w > 1.0f);
            lo += (b.x > -1.0f) + (b.y > -1.0f) + (b.z > -1.0f) + (b.w > -1.0f);
            unsigned m = (b.x > 0.0f ? 1u : 0u) | (b.y > 0.0f ? 2u : 0u) |
                         (b.z > 0.0f ? 4u : 0u) | (b.w > 0.0f ? 8u : 0u);
            if (m) {
                minY = min(minY, y); maxY = max(maxY, y);
                minX = min(minX, x + (__ffs(m) - 1));
                maxX = max(maxX, x + (31 - __clz(m)));
            }
        }
    }

    #pragma unroll
    for (int off = 16; off; off >>= 1) {
        hi += __shfl_down_sync(0xFFFFFFFFu, hi, off);
        lo += __shfl_down_sync(0xFFFFFFFFu, lo, off);
        minX = min(minX, __shfl_down_sync(0xFFFFFFFFu, minX, off));
        maxX = max(maxX, __shfl_down_sync(0xFFFFFFFFu, maxX, off));
        minY = min(minY, __shfl_down_sync(0xFFFFFFFFu, minY, off));
        maxY = max(maxY, __shfl_down_sync(0xFFFFFFFFu, maxY, off));
    }

    __shared__ int s[6][8];
    int wid = threadIdx.x >> 5, lane = threadIdx.x & 31;
    if (lane == 0) {
        s[0][wid] = hi; s[1][wid] = lo;
        s[2][wid] = minX; s[3][wid] = maxX;
        s[4][wid] = minY; s[5][wid] = maxY;
    }
    __syncthreads();
    if (threadIdx.x == 0) {
        int Hc = 0, Lc = 0, mX = WW, MX = -1, mY = HH, MY = -1;
        #pragma unroll
        for (int w = 0; w < 8; w++) {
            Hc += s[0][w]; Lc += s[1][w];
            mX = min(mX, s[2][w]); MX = max(MX, s[3][w]);
            mY = min(mY, s[4][w]); MY = max(MY, s[5][w]);
        }
        float stab = (float)Hc / fmaxf((float)Lc, 1.0f);
        float sc = iou[n];
        g_valid[n] = (sc > 0.88f) && (stab >= 0.95f);
        float x0, y0, x1, y1;
        if (MY < 0) { x0 = y0 = x1 = y1 = 0.0f; }
        else { x0 = (float)mX; y0 = (float)mY; x1 = (float)MX; y1 = (float)MY; }
        g_boxes[n * 4 + 0] = x0;
        g_boxes[n * 4 + 1] = y0;
        g_boxes[n * 4 + 2] = x1;
        g_boxes[n * 4 + 3] = y1;
    }
}

// ---------------------------------------------------------------------------
// Kernel B: NMS. Compact valid -> rank-sort -> warp-0 register greedy with
// bitmask ownership (iterations = number of KEPT boxes, not M).
// Also emits compacted kept-mask list for the output kernel + tail outputs.
// ---------------------------------------------------------------------------
__global__ __launch_bounds__(256) void nms_kernel(const float* __restrict__ iou,
                                                  float* __restrict__ out,
                                                  int write_tail) {
    __shared__ float  sScore[NM];
    __shared__ float4 sBox[NM];
    __shared__ short  sIdx[NM];       // unordered compacted valid indices
    __shared__ short  sOrder[NM];     // valid indices in rank order
    __shared__ unsigned char sKO[NM]; // keep by original index
    __shared__ int sM;

    int t = threadIdx.x;
    if (t == 0) { sM = 0; g_kcnt = 0; }
    for (int i = t; i < NM; i += 256) {
        sScore[i] = iou[i];
        sBox[i] = make_float4(g_boxes[i * 4 + 0], g_boxes[i * 4 + 1],
                              g_boxes[i * 4 + 2], g_boxes[i * 4 + 3]);
        sKO[i] = 0;
    }
    __syncthreads();
    for (int i = t; i < NM; i += 256) {
        if (g_valid[i]) {
            int pos = atomicAdd(&sM, 1);
            sIdx[pos] = (short)i;
        }
    }
    __syncthreads();
    int M = sM;

    // rank among valid entries (stable: ties -> lower original index first)
    for (int s = t; s < M; s += 256) {
        int i = sIdx[s];
        float ki = sScore[i];
        int rank = 0;
        for (int u = 0; u < M; u++) {
            int j = sIdx[u];
            float kj = sScore[j];
            rank += (kj > ki) || (kj == ki && j < i);
        }
        sOrder[rank] = (short)i;
    }
    __syncthreads();

    // warp-0 greedy: lane owns sorted positions {b*32+lane}, alive bitmask in reg.
    if (t < 32) {
        int lane = t;
        unsigned alive = 0;
        #pragma unroll
        for (int b = 0; b < 32; b++)
            if (b * 32 + lane < M) alive |= (1u << b);
        unsigned keepbits = 0;

        while (true) {
            int cand = alive ? ((__ffs(alive) - 1) * 32 + lane) : 0x7FFFFFFF;
            #pragma unroll
            for (int off = 16; off; off >>= 1)
                cand = min(cand, __shfl_xor_sync(0xFFFFFFFFu, cand, off));
            if (cand == 0x7FFFFFFF) break;
            int i = cand;
            if ((i & 31) == lane) {
                keepbits |= (1u << (i >> 5));
                alive &= ~(1u << (i >> 5));
            }
            float4 bi = sBox[sOrder[i]];   // broadcast read
            float areaA = fmaxf(bi.z - bi.x, 0.0f) * fmaxf(bi.w - bi.y, 0.0f);
            unsigned m = alive;
            while (m) {
                int b = __ffs(m) - 1; m &= m - 1;
                int p = b * 32 + lane;
                float4 bj = sBox[sOrder[p]];
                float x0 = fmaxf(bi.x, bj.x), y0 = fmaxf(bi.y, bj.y);
                float x1 = fminf(bi.z, bj.z), y1 = fminf(bi.w, bj.w);
                float inter = fmaxf(x1 - x0, 0.0f) * fmaxf(y1 - y0, 0.0f);
                float areaB = fmaxf(bj.z - bj.x, 0.0f) * fmaxf(bj.w - bj.y, 0.0f);
                float v = inter / fmaxf(areaA + areaB - inter, 1e-6f);
                if (v > 0.7f) alive &= ~(1u << b);
            }
        }

        // record kept boxes (order in list irrelevant)
        while (keepbits) {
            int b = __ffs(keepbits) - 1; keepbits &= keepbits - 1;
            int pos = b * 32 + lane;
            int orig = sOrder[pos];
            sKO[orig] = 1;
            int slot = atomicAdd(&g_kcnt, 1);
            g_klist[slot] = orig;
            g_kgate[slot] = sScore[orig];
        }
    }
    __syncthreads();

    size_t base = (size_t)NM * HWsz;
    if (write_tail) {
        for (int i = t; i < NM; i += 256) {
            out[base + i] = sKO[i] ? 1.0f : 0.0f;
            float4 b = sBox[i];
            out[base + NM + (size_t)i * 4 + 0] = b.x;
            out[base + NM + (size_t)i * 4 + 1] = b.y;
            out[base + NM + (size_t)i * 4 + 2] = b.z;
            out[base + NM + (size_t)i * 4 + 3] = b.w;
        }
    }
}

// ---------------------------------------------------------------------------
// Kernel C: kept-mask output only. Zeros already written by async memset.
// grid (16, NM); blocks with y >= g_kcnt exit after one load.
// ---------------------------------------------------------------------------
__global__ __launch_bounds__(256) void keptout_kernel(const float* __restrict__ logits,
                                                      float* __restrict__ out) {
    int y = blockIdx.y;
    if (y >= g_kcnt) return;
    int n = g_klist[y];
    float g = g_kgate[y];
    size_t base = (size_t)n * HWsz;
    int i0 = blockIdx.x * 1024 + threadIdx.x;   // float4 index, 4 chunks of 256
    const float4* p = (const float4*)(logits + base);
    float4* o = (float4*)(out + base);
    float4 v[4];
    #pragma unroll
    for (int j = 0; j < 4; j++) v[j] = p[i0 + j * 256];
    #pragma unroll
    for (int j = 0; j < 4; j++) {
        v[j].x = g / (1.0f + __expf(-v[j].x));
        v[j].y = g / (1.0f + __expf(-v[j].y));
        v[j].z = g / (1.0f + __expf(-v[j].z));
        v[j].w = g / (1.0f + __expf(-v[j].w));
        o[i0 + j * 256] = v[j];
    }
}

extern "C" void kernel_launch(void* const* d_in, const int* in_sizes, int n_in,
                              void* d_out, int out_size) {
    const float* logits = (const float*)d_in[0];  // [1024,256,256]
    const float* iou    = (const float*)d_in[1];  // [1024]
    float* out = (float*)d_out;

    int write_tail = (out_size >= NM * HWsz + NM + NM * 4) ? 1 : 0;
    size_t mask_bytes = (size_t)NM * HWsz * sizeof(float);
    if ((size_t)out_size * sizeof(float) < mask_bytes)
        mask_bytes = (size_t)out_size * sizeof(float);

    // One-time host-side resources (no device memory involved).
    static cudaStream_t s1 = nullptr;
    static cudaEvent_t evFork = nullptr, evJoin = nullptr;
    if (s1 == nullptr) {
        cudaStreamCreateWithFlags(&s1, cudaStreamNonBlocking);
        cudaEventCreateWithFlags(&evFork, cudaEventDisableTiming);
        cudaEventCreateWithFlags(&evJoin, cudaEventDisableTiming);
    }

    // Fork: zero-fill 268MB mask region on s1, concurrent with stats on s0.
    cudaEventRecord(evFork, 0);
    cudaStreamWaitEvent(s1, evFork, 0);
    cudaMemsetAsync(d_out, 0, mask_bytes, s1);

    stats_kernel<<<NM, 256>>>(logits, iou);

    // Join s1 back into the capture/legacy stream.
    cudaEventRecord(evJoin, s1);
    cudaStreamWaitEvent(0, evJoin, 0);

    nms_kernel<<<1, 256>>>(iou, out, write_tail);
    dim3 grid(16, NM);
    keptout_kernel<<<grid, 256>>>(logits, out);
}